// round 5
// baseline (speedup 1.0000x reference)
#include <cuda_runtime.h>
#include <cuda_bf16.h>

// CRFConstituency: inside-outside marginals of CYK CRF.
// B=8, S=256. scores: [B,S,S] f32, mask: [B,S,S] bool (fixed triu k=1 -> lens=255).
// Output: marginals [B,S,S] f32 (strict upper triangle = g, else 0).
//
// One persistent CTA per batch. Packed upper triangle of the inside table s
// lives in shared memory (130,560 B). 255 forward width steps + 254 backward
// width steps, separated only by __syncthreads. Backward is a gather (no
// atomics) using A[i,j] = log g[i,j] + sc[i,j] - s[i,j], kept in two global
// scratch copies (row-major and transposed) for coalesced reads.
//
// R4 fix: strided triangle-offset recurrence across a 32-lane chunk is
//   off(k+32) = off(k) + 7632 - 32k   (NOT 7664 - 32k; the extra -32 comes
// from the (j-k-1) in-row term). The old constant overran the smem triangle
// by up to 224 floats at wide spans -> illegal memory access.

#define SS 256
#define BB 8
#define TRI ((SS*(SS-1))/2)          // 32640 floats
#define SMEM_BYTES (TRI*4)           // 130560 bytes
#define NEGF (-1e30f)

// global scratch: A row-major copy and column(transposed) copy
__device__ float g_Ar[BB][SS][SS];
__device__ float g_Ac[BB][SS][SS];

__device__ __forceinline__ int tri_base(int i) {
    // row i of packed strict-upper triangle holds j = i+1 .. S-1
    return i * (SS - 1) - ((i * (i - 1)) >> 1);
}

__global__ __launch_bounds__(1024, 1)
void crf_inside_outside_kernel(const float* __restrict__ scores,
                               float* __restrict__ out)
{
    extern __shared__ float s_tri[];     // packed inside table, TRI floats

    const int b    = blockIdx.x;
    const float* sc = scores + b * SS * SS;
    float* mout     = out    + b * SS * SS;

    const int tid  = threadIdx.x;
    const int lane = tid & 31;
    const int wid  = tid >> 5;           // 32 warps

    // ---------------- forward: width 1 init ----------------
    for (int i = tid; i < SS - 1; i += blockDim.x)
        s_tri[tri_base(i)] = sc[i * SS + i + 1];
    __syncthreads();

    // ---------------- forward: widths 2 .. S-1 ----------------
    for (int w = 2; w <= SS - 1; ++w) {
        const int nspans = SS - w;
        const int nterms = w - 1;
        const int nch    = (nterms + 31) >> 5;   // <= 8 chunks of 32

        for (int sp = wid; sp < nspans; sp += 32) {
            const int i = sp;
            const int j = i + w;
            const int rb_i = tri_base(i);

            // term k = i+1 .. j-1 :  t = s[i,k] + s[k,j]
            // operand A: off1 = rb_i + (k-i-1)          (contiguous in k)
            // operand B: off2 = tri_base(k) + (j-k-1)
            //   off2(k+32) = off2(k) + 7632 - 32*k      (S=256)
            int k0   = i + 1 + lane;
            int off1 = rb_i + lane;
            int off2 = tri_base(k0) + (j - k0 - 1);
            int kk   = k0;

            float tv[8];
            float mx = NEGF;
            #pragma unroll
            for (int c = 0; c < 8; ++c) {
                tv[c] = NEGF;
                if (c < nch) {
                    if (kk < j)
                        tv[c] = s_tri[off1] + s_tri[off2];
                    off1 += 32;
                    off2 += 7632 - (kk << 5);
                    kk   += 32;
                }
                mx = fmaxf(mx, tv[c]);
            }
            #pragma unroll
            for (int o = 16; o; o >>= 1)
                mx = fmaxf(mx, __shfl_xor_sync(0xffffffffu, mx, o));

            float acc = 0.f;
            #pragma unroll
            for (int c = 0; c < 8; ++c)
                if (c < nch) acc += __expf(tv[c] - mx);
            #pragma unroll
            for (int o = 16; o; o >>= 1)
                acc += __shfl_xor_sync(0xffffffffu, acc, o);

            if (lane == 0)
                s_tri[rb_i + (j - i - 1)] = sc[i * SS + j] + mx + __logf(acc);
        }
        __syncthreads();
    }

    // ---------------- backward init ----------------
    // zero lower triangle + diagonal of output (d_out arrives poisoned)
    for (int idx = tid; idx < SS * SS; idx += blockDim.x) {
        const int i = idx >> 8;
        const int j = idx & 255;
        if (j <= i) mout[idx] = 0.f;
    }
    // top span (0, S-1): g = 1
    if (tid == 0) {
        const float s_top = s_tri[tri_base(0) + (SS - 2)];
        mout[SS - 1] = 1.0f;
        const float A = sc[SS - 1] - s_top;      // log(1)=0
        g_Ar[b][0][SS - 1] = A;
        g_Ac[b][SS - 1][0] = A;
    }
    __syncthreads();

    // ---------------- backward: widths S-2 .. 1 ----------------
    // g[a,bc] = sum_{j>bc} exp(s_ab + s[bc,j] + Ar[a][j])
    //         + sum_{i<a}  exp(s_ab + s[i,a]  + Ac[bc][i])
    for (int w = SS - 2; w >= 1; --w) {
        const int nspans = SS - w;
        for (int sp = wid; sp < nspans; sp += 32) {
            const int a  = sp;
            const int bc = a + w;
            const float s_ab = s_tri[tri_base(a) + (bc - a - 1)];

            float acc = 0.f;

            // segment 1: parents (a, j), j = bc+1 .. S-1 (this span is LEFT child)
            {
                const int rb_bc = tri_base(bc);
                const float* Ar = &g_Ar[b][a][0];
                for (int j = bc + 1 + lane; j < SS; j += 32) {
                    const float x = s_tri[rb_bc + (j - bc - 1)] + Ar[j];
                    acc += __expf(s_ab + x);
                }
            }
            // segment 2: parents (i, bc), i = 0 .. a-1 (this span is RIGHT child)
            {
                const float* Ac = &g_Ac[b][bc][0];
                int i   = lane;
                int off = tri_base(i) + (a - i - 1);
                while (i < a) {
                    acc += __expf(s_ab + s_tri[off] + Ac[i]);
                    off += 7632 - (i << 5);
                    i   += 32;
                }
            }

            #pragma unroll
            for (int o = 16; o; o >>= 1)
                acc += __shfl_xor_sync(0xffffffffu, acc, o);

            if (lane == 0) {
                const float g = acc;
                mout[a * SS + bc] = g;
                const float A = __logf(g) + sc[a * SS + bc] - s_ab;
                g_Ar[b][a][bc] = A;
                g_Ac[b][bc][a] = A;
            }
        }
        __syncthreads();
    }
}

extern "C" void kernel_launch(void* const* d_in, const int* in_sizes, int n_in,
                              void* d_out, int out_size)
{
    (void)in_sizes; (void)n_in; (void)out_size;
    const float* scores = (const float*)d_in[0];
    // d_in[1] is the mask; for this problem it is the fixed triu(k=1) mask,
    // so lens == S-1 for every batch element (hardcoded).
    float* out = (float*)d_out;

    cudaFuncSetAttribute(crf_inside_outside_kernel,
                         cudaFuncAttributeMaxDynamicSharedMemorySize, SMEM_BYTES);
    crf_inside_outside_kernel<<<BB, 1024, SMEM_BYTES>>>(scores, out);
}

// round 6
// speedup vs baseline: 2.6533x; 2.6533x over previous
#include <cuda_runtime.h>
#include <cuda_bf16.h>
#include <cstdint>

// CRFConstituency inside-outside, B=8, S=256, lens==255 (fixed triu mask).
// R6: 8-CTA cluster per batch (grid=64). Each CTA holds a FULL smem replica of
// the packed inside triangle (130,560 B). Per width step, warp g handles span
// sp = wid*8 + rank (one span per warp across the cluster), lane0 broadcasts
// the new value to all 8 replicas via mapa + st.shared::cluster, then
// barrier.cluster separates steps. Backward gather uses A[i,j] = log g + sc - s
// in global scratch, accessed with .cg (L2-coherent; L1 is not coherent
// across the SMs of the cluster).

#define SS 256
#define BB 8
#define CLUSTER 8
#define TRI ((SS*(SS-1))/2)          // 32640 floats
#define SMEM_BYTES (TRI*4)           // 130560 bytes
#define NEGF (-1e30f)

__device__ float g_Ar[BB][SS][SS];
__device__ float g_Ac[BB][SS][SS];

__device__ __forceinline__ int tri_base(int i) {
    return i * (SS - 1) - ((i * (i - 1)) >> 1);
}

__device__ __forceinline__ uint32_t smem_u32(const void* p) {
    uint32_t a;
    asm("{ .reg .u64 t; cvta.to.shared.u64 t, %1; cvt.u32.u64 %0, t; }"
        : "=r"(a) : "l"(p));
    return a;
}

__device__ __forceinline__ void st_peer(uint32_t local_addr, int peer, float v) {
    uint32_t rem;
    asm volatile("mapa.shared::cluster.u32 %0, %1, %2;"
                 : "=r"(rem) : "r"(local_addr), "r"(peer));
    asm volatile("st.shared::cluster.f32 [%0], %1;" :: "r"(rem), "f"(v));
}

__device__ __forceinline__ void cluster_sync_all() {
    asm volatile("barrier.cluster.arrive.aligned;" ::: "memory");
    asm volatile("barrier.cluster.wait.aligned;" ::: "memory");
}

__global__ __launch_bounds__(1024, 1) __cluster_dims__(CLUSTER, 1, 1)
void crf_inside_outside_cluster(const float* __restrict__ scores,
                                float* __restrict__ out)
{
    extern __shared__ float s_tri[];     // full packed triangle replica

    const int b    = blockIdx.x >> 3;    // cluster index = batch
    uint32_t rank;
    asm("mov.u32 %0, %%cluster_ctarank;" : "=r"(rank));

    const float* sc = scores + b * SS * SS;
    float* mout     = out    + b * SS * SS;

    const int tid  = threadIdx.x;
    const int lane = tid & 31;
    const int wid  = tid >> 5;           // 32 warps
    const int sp_of_warp = wid * CLUSTER + (int)rank;   // this warp's span id

    // ---------------- forward width-1 init (each CTA fills its replica) ----
    for (int i = tid; i < SS - 1; i += blockDim.x)
        s_tri[tri_base(i)] = sc[i * SS + i + 1];
    __syncthreads();

    // ---------------- forward widths 2..255 ----------------
    for (int w = 2; w <= SS - 1; ++w) {
        const int nspans = SS - w;
        const int sp = sp_of_warp;
        if (sp < nspans) {
            const int i = sp;
            const int j = i + w;
            const int rb_i = tri_base(i);
            const int nterms = w - 1;
            const int nch    = (nterms + 31) >> 5;

            int k0   = i + 1 + lane;
            int off1 = rb_i + lane;
            int off2 = tri_base(k0) + (j - k0 - 1);
            int kk   = k0;

            float tv[8];
            float mx = NEGF;
            #pragma unroll
            for (int c = 0; c < 8; ++c) {
                tv[c] = NEGF;
                if (c < nch) {
                    if (kk < j)
                        tv[c] = s_tri[off1] + s_tri[off2];
                    off1 += 32;
                    off2 += 7632 - (kk << 5);
                    kk   += 32;
                }
                mx = fmaxf(mx, tv[c]);
            }
            #pragma unroll
            for (int o = 16; o; o >>= 1)
                mx = fmaxf(mx, __shfl_xor_sync(0xffffffffu, mx, o));

            float acc = 0.f;
            #pragma unroll
            for (int c = 0; c < 8; ++c)
                if (c < nch) acc += __expf(tv[c] - mx);
            #pragma unroll
            for (int o = 16; o; o >>= 1)
                acc += __shfl_xor_sync(0xffffffffu, acc, o);

            if (lane == 0) {
                const float val = sc[i * SS + j] + mx + __logf(acc);
                const uint32_t laddr = smem_u32(&s_tri[rb_i + (j - i - 1)]);
                #pragma unroll
                for (int p = 0; p < CLUSTER; ++p)
                    st_peer(laddr, p, val);
            }
        }
        cluster_sync_all();
    }

    // ---------------- backward init ----------------
    // zero lower triangle + diagonal of output (split across the 8 CTAs)
    for (int idx = ((int)rank << 13) + tid; idx < ((int)rank + 1) << 13; idx += 1024) {
        const int i = idx >> 8;
        const int j = idx & 255;
        if (j <= i) mout[idx] = 0.f;
    }
    if (rank == 0 && tid == 0) {
        const float s_top = s_tri[tri_base(0) + (SS - 2)];
        mout[SS - 1] = 1.0f;
        const float A = sc[SS - 1] - s_top;      // log g = 0
        __stcg(&g_Ar[b][0][SS - 1], A);
        __stcg(&g_Ac[b][SS - 1][0], A);
    }
    cluster_sync_all();

    // ---------------- backward widths 254..1 ----------------
    // g[a,bc] = sum_{j>bc} exp(s_ab + s[bc,j] + Ar[a][j])
    //         + sum_{i<a}  exp(s_ab + s[i,a]  + Ac[bc][i])
    for (int w = SS - 2; w >= 1; --w) {
        const int nspans = SS - w;
        const int sp = sp_of_warp;
        if (sp < nspans) {
            const int a  = sp;
            const int bc = a + w;
            const float s_ab = s_tri[tri_base(a) + (bc - a - 1)];

            float acc = 0.f;

            // segment 1: parents (a, j), j = bc+1 .. S-1
            {
                const int rb_bc = tri_base(bc);
                const float* Ar = &g_Ar[b][a][0];
                for (int j = bc + 1 + lane; j < SS; j += 32) {
                    const float x = s_tri[rb_bc + (j - bc - 1)] + __ldcg(Ar + j);
                    acc += __expf(s_ab + x);
                }
            }
            // segment 2: parents (i, bc), i = 0 .. a-1
            {
                const float* Ac = &g_Ac[b][bc][0];
                int i   = lane;
                int off = tri_base(i) + (a - i - 1);
                while (i < a) {
                    acc += __expf(s_ab + s_tri[off] + __ldcg(Ac + i));
                    off += 7632 - (i << 5);
                    i   += 32;
                }
            }

            #pragma unroll
            for (int o = 16; o; o >>= 1)
                acc += __shfl_xor_sync(0xffffffffu, acc, o);

            if (lane == 0) {
                const float g = acc;
                mout[a * SS + bc] = g;
                const float A = __logf(g) + sc[a * SS + bc] - s_ab;
                __stcg(&g_Ar[b][a][bc], A);
                __stcg(&g_Ac[b][bc][a], A);
            }
        }
        cluster_sync_all();
    }
}

extern "C" void kernel_launch(void* const* d_in, const int* in_sizes, int n_in,
                              void* d_out, int out_size)
{
    (void)in_sizes; (void)n_in; (void)out_size;
    const float* scores = (const float*)d_in[0];
    float* out = (float*)d_out;

    cudaFuncSetAttribute(crf_inside_outside_cluster,
                         cudaFuncAttributeMaxDynamicSharedMemorySize, SMEM_BYTES);
    crf_inside_outside_cluster<<<BB * CLUSTER, 1024, SMEM_BYTES>>>(scores, out);
}